// round 7
// baseline (speedup 1.0000x reference)
#include <cuda_runtime.h>
#include <cuda_bf16.h>
#include <cstdint>

// Integration_4123168604342
// x: (T=128, B=4, E=10000, F=16) f32, dummy_index: int scalar
// out: (128, 4, 10000, 15) f32 = tanh(cumsum_T(f * dt))
//
// R7: scalar mapping (16 lanes per (b,e) group, lane=channel) — best so far —
// with the SHFL removed from the recurrence. The t-channel value is loaded
// directly (broadcast LDG to the same 64B the data load fetches: L1 hit, no
// extra DRAM sectors) and prefetched DEPTH rows ahead in the rotating
// pipeline, so the per-row consume step has ZERO exposed memory latency.

#define T_DIM   128
#define B_DIM   4
#define E_DIM   10000
#define F_DIM   16
#define FO_DIM  15
#define DEPTH   8
#define BE_DIM  (B_DIM * E_DIM)               // 40000 groups
#define STRIDE_T   ((size_t)BE_DIM * F_DIM)   // 640000 floats per t (input)
#define STRIDE_TO  ((size_t)BE_DIM * FO_DIM)  // 600000 floats per t (output)

__device__ __forceinline__ float tanh_fast(float x) {
    float y;
    asm("tanh.approx.f32 %0, %1;" : "=f"(y) : "f"(x));
    return y;
}

__global__ __launch_bounds__(256)
void integration_kernel(const float* __restrict__ x,
                        const int* __restrict__ didx,
                        float* __restrict__ out) {
    const int gid   = blockIdx.x * blockDim.x + threadIdx.x;
    const int group = gid >> 4;       // (b,e) flat index
    const int lane  = gid & 15;       // channel

    const int d = *didx;              // dummy (time) channel (uniform)
    const bool is_t = (lane == d);
    const int oc = lane - (lane > d ? 1 : 0);   // output channel for non-t lanes

    const float* __restrict__ xp = x + (size_t)group * F_DIM + lane;  // my channel
    const float* __restrict__ tp = x + (size_t)group * F_DIM + d;     // t channel (uniform/group)
    float* __restrict__ op = out + (size_t)group * FO_DIM + oc;

    // ---- prologue: rows 0..7 of data AND t-channel in flight ----
    float b0 = xp[0];
    float b1 = xp[STRIDE_T];
    float b2 = xp[2 * STRIDE_T];
    float b3 = xp[3 * STRIDE_T];
    float b4 = xp[4 * STRIDE_T];
    float b5 = xp[5 * STRIDE_T];
    float b6 = xp[6 * STRIDE_T];
    float b7 = xp[7 * STRIDE_T];
    float c0 = tp[0];
    float c1 = tp[STRIDE_T];
    float c2 = tp[2 * STRIDE_T];
    float c3 = tp[3 * STRIDE_T];
    float c4 = tp[4 * STRIDE_T];
    float c5 = tp[5 * STRIDE_T];
    float c6 = tp[6 * STRIDE_T];
    float c7 = tp[7 * STRIDE_T];

    // t = 0: dt0 = t[0] + t[1]
    float acc = b0 * (c0 + c1);
    if (!is_t) op[0] = tanh_fast(acc);
    float prev_t = c0;

    // consume row (base+k) from (bv, cv), then reload both from row (base+k+DEPTH)
#define STEP(bv, cv, k) do {                                                \
        acc = fmaf((bv), (cv) - prev_t, acc);                               \
        if (!is_t) op[(size_t)(base + (k)) * STRIDE_TO] = tanh_fast(acc);   \
        prev_t = (cv);                                                      \
        (bv) = xp[(size_t)(base + (k) + DEPTH) * STRIDE_T];                 \
        (cv) = tp[(size_t)(base + (k) + DEPTH) * STRIDE_T];                 \
    } while (0)

#define STEP_NOLOAD(bv, cv, k) do {                                         \
        acc = fmaf((bv), (cv) - prev_t, acc);                               \
        if (!is_t) op[(size_t)(base + (k)) * STRIDE_TO] = tanh_fast(acc);   \
        prev_t = (cv);                                                      \
    } while (0)

    // ---- steady state: rows 0..119 consumed, rows 8..127 reloaded ----
    #pragma unroll 1
    for (int base = 0; base < T_DIM - DEPTH; base += DEPTH) {
        if (base > 0) {
            STEP(b0, c0, 0);
        } else {
            // row 0 already done at prologue; just refill slot 0
            b0 = xp[(size_t)DEPTH * STRIDE_T];
            c0 = tp[(size_t)DEPTH * STRIDE_T];
        }
        STEP(b1, c1, 1);
        STEP(b2, c2, 2);
        STEP(b3, c3, 3);
        STEP(b4, c4, 4);
        STEP(b5, c5, 5);
        STEP(b6, c6, 6);
        STEP(b7, c7, 7);
    }

    // ---- epilogue: rows 120..127 ----
    {
        const int base = T_DIM - DEPTH;
        STEP_NOLOAD(b0, c0, 0);
        STEP_NOLOAD(b1, c1, 1);
        STEP_NOLOAD(b2, c2, 2);
        STEP_NOLOAD(b3, c3, 3);
        STEP_NOLOAD(b4, c4, 4);
        STEP_NOLOAD(b5, c5, 5);
        STEP_NOLOAD(b6, c6, 6);
        STEP_NOLOAD(b7, c7, 7);
    }

#undef STEP
#undef STEP_NOLOAD
}

extern "C" void kernel_launch(void* const* d_in, const int* in_sizes, int n_in,
                              void* d_out, int out_size) {
    const float* x   = (const float*)d_in[0];
    const int* didx  = (const int*)d_in[1];
    float* out       = (float*)d_out;

    const int total_threads = BE_DIM * 16;        // 640000
    const int block = 256;
    const int grid = total_threads / block;       // 2500 exact, no tail guard
    integration_kernel<<<grid, block>>>(x, didx, out);
}

// round 8
// speedup vs baseline: 1.1317x; 1.1317x over previous
#include <cuda_runtime.h>
#include <cuda_bf16.h>
#include <cstdint>

// Integration_4123168604342
// x: (T=128, B=4, E=10000, F=16) f32, dummy_index: int scalar
// out: (128, 4, 10000, 15) f32 = tanh(cumsum_T(f * dt))
//
// R8: exact R5 structure (best: scalar mapping, depth-16 rotating pipeline)
// + streaming cache hints: __ldcs on the input stream, __stcs on the output
// stream. Neither stream has reuse; evict-first reads free L2 capacity to
// buffer dirty output lines, batching DRAM writebacks and cutting r/w
// turnaround — the hypothesized cause of the 106us / DRAM-70% plateau.

#define T_DIM   128
#define B_DIM   4
#define E_DIM   10000
#define F_DIM   16
#define FO_DIM  15
#define DEPTH   16
#define BE_DIM  (B_DIM * E_DIM)               // 40000 groups
#define STRIDE_T   ((size_t)BE_DIM * F_DIM)   // 640000 floats per t (input)
#define STRIDE_TO  ((size_t)BE_DIM * FO_DIM)  // 600000 floats per t (output)

__device__ __forceinline__ float tanh_fast(float x) {
    float y;
    asm("tanh.approx.f32 %0, %1;" : "=f"(y) : "f"(x));
    return y;
}

__global__ __launch_bounds__(256)
void integration_kernel(const float* __restrict__ x,
                        const int* __restrict__ didx,
                        float* __restrict__ out) {
    const int gid   = blockIdx.x * blockDim.x + threadIdx.x;
    const int group = gid >> 4;       // (b,e) flat index
    const int lane  = gid & 15;       // channel
    if (group >= BE_DIM) return;

    const int d = *didx;              // dummy (time) channel
    const bool is_t = (lane == d);
    const int oc = lane - (lane > d ? 1 : 0);   // output channel for non-t lanes

    const float* __restrict__ xp = x + (size_t)group * F_DIM + lane;
    float* __restrict__ op = out + (size_t)group * FO_DIM + oc;

    // ---- prologue: rows 0..15 in flight ----
    float b0  = __ldcs(xp);
    float b1  = __ldcs(xp + STRIDE_T);
    float b2  = __ldcs(xp + 2 * STRIDE_T);
    float b3  = __ldcs(xp + 3 * STRIDE_T);
    float b4  = __ldcs(xp + 4 * STRIDE_T);
    float b5  = __ldcs(xp + 5 * STRIDE_T);
    float b6  = __ldcs(xp + 6 * STRIDE_T);
    float b7  = __ldcs(xp + 7 * STRIDE_T);
    float b8  = __ldcs(xp + 8 * STRIDE_T);
    float b9  = __ldcs(xp + 9 * STRIDE_T);
    float b10 = __ldcs(xp + 10 * STRIDE_T);
    float b11 = __ldcs(xp + 11 * STRIDE_T);
    float b12 = __ldcs(xp + 12 * STRIDE_T);
    float b13 = __ldcs(xp + 13 * STRIDE_T);
    float b14 = __ldcs(xp + 14 * STRIDE_T);
    float b15 = __ldcs(xp + 15 * STRIDE_T);

    const float t0 = __shfl_sync(0xFFFFFFFFu, b0, d, 16);
    const float t1 = __shfl_sync(0xFFFFFFFFu, b1, d, 16);

    // t = 0: dt0 = t[0] + t[1]
    float acc = b0 * (t0 + t1);
    if (!is_t) __stcs(op, tanh_fast(acc));
    float prev_t = t0;

    // consume buffer bv as row (base+k), then reload bv from row (base+k+DEPTH)
#define STEP(bv, k) do {                                                       \
        const float tc = __shfl_sync(0xFFFFFFFFu, (bv), d, 16);                \
        acc = fmaf((bv), tc - prev_t, acc);                                    \
        if (!is_t) __stcs(op + (size_t)(base + (k)) * STRIDE_TO,               \
                          tanh_fast(acc));                                     \
        prev_t = tc;                                                           \
        (bv) = __ldcs(xp + (size_t)(base + (k) + DEPTH) * STRIDE_T);           \
    } while (0)

#define STEP_NOLOAD(bv, k) do {                                                \
        const float tc = __shfl_sync(0xFFFFFFFFu, (bv), d, 16);                \
        acc = fmaf((bv), tc - prev_t, acc);                                    \
        if (!is_t) __stcs(op + (size_t)(base + (k)) * STRIDE_TO,               \
                          tanh_fast(acc));                                     \
        prev_t = tc;                                                           \
    } while (0)

    // ---- steady state: rows 0..111 consumed, rows 16..127 reloaded ----
    #pragma unroll 1
    for (int base = 0; base < T_DIM - DEPTH; base += DEPTH) {
        if (base > 0) STEP(b0, 0);
        else          b0 = __ldcs(xp + (size_t)DEPTH * STRIDE_T); // row 0 done
        STEP(b1,  1);
        STEP(b2,  2);
        STEP(b3,  3);
        STEP(b4,  4);
        STEP(b5,  5);
        STEP(b6,  6);
        STEP(b7,  7);
        STEP(b8,  8);
        STEP(b9,  9);
        STEP(b10, 10);
        STEP(b11, 11);
        STEP(b12, 12);
        STEP(b13, 13);
        STEP(b14, 14);
        STEP(b15, 15);
    }

    // ---- epilogue: rows 112..127, no more loads ----
    {
        const int base = T_DIM - DEPTH;
        STEP_NOLOAD(b0,  0);
        STEP_NOLOAD(b1,  1);
        STEP_NOLOAD(b2,  2);
        STEP_NOLOAD(b3,  3);
        STEP_NOLOAD(b4,  4);
        STEP_NOLOAD(b5,  5);
        STEP_NOLOAD(b6,  6);
        STEP_NOLOAD(b7,  7);
        STEP_NOLOAD(b8,  8);
        STEP_NOLOAD(b9,  9);
        STEP_NOLOAD(b10, 10);
        STEP_NOLOAD(b11, 11);
        STEP_NOLOAD(b12, 12);
        STEP_NOLOAD(b13, 13);
        STEP_NOLOAD(b14, 14);
        STEP_NOLOAD(b15, 15);
    }

#undef STEP
#undef STEP_NOLOAD
}

extern "C" void kernel_launch(void* const* d_in, const int* in_sizes, int n_in,
                              void* d_out, int out_size) {
    const float* x   = (const float*)d_in[0];
    const int* didx  = (const int*)d_in[1];
    float* out       = (float*)d_out;

    const int total_threads = BE_DIM * 16;        // 640000
    const int block = 256;
    const int grid = (total_threads + block - 1) / block;  // 2500
    integration_kernel<<<grid, block>>>(x, didx, out);
}